// round 5
// baseline (speedup 1.0000x reference)
#include <cuda_runtime.h>
#include <math.h>

// Fixed problem shapes
#define BB 8
#define CC 3
#define HF 1024
#define WF 2048
#define MM 32
#define HH 128
#define WW 256
#define HW (HH*WW)

// padded pooled image (2-px zero border each side)
#define PW (WW+4)
#define PH (HH+4)

#define NCH 64
#define CHSZ (HW/NCH)              // 512 samples per chunk

#define BORDER_PER_B (4*PW + 4*HH)             // 1552
#define BORDER_ELEMS (BB*BORDER_PER_B)         // 12416

// combined-kernel grid roles
#define POOL_PB   384              // pool blocks per batch (98304 threads / 256)
#define BLEND_PB  128              // blend blocks per batch
#define BATCH_BLKS (POOL_PB + BLEND_PB)

// ---------------- scratch ----------------------------------------------------
__device__ float4 g_imgp[BB*PH*PW];          // padded pooled image
__device__ float  g_Hm  [BB*MM*6];           // homography top-2 rows
__device__ float  g_part[BB*MM*5*NCH];       // partial sums [bm][5][NCH]
__device__ int    g_cnt [BB];                // pool completion counters
__device__ int    g_flag;                    // Hm + border ready

// ---------------- kernel 1: plane partials (+ counter reset) -----------------
__global__ __launch_bounds__(256) void plane_partial_kernel(const float* __restrict__ masks,
                                                            const float* __restrict__ disp,
                                                            const float* __restrict__ intrs,
                                                            const float* __restrict__ baseline) {
    __shared__ float4 sdn[CHSZ];
    int blk = blockIdx.x;
    int tid = threadIdx.x;
    if (blk == 0) {                 // reset sync vars for this replay (stream-ordered)
        if (tid < BB) g_cnt[tid] = 0;
        if (tid == BB) g_flag = 0;
    }

    int bb = blk / NCH, ch = blk % NCH;
    float f  = 0.5f*(intrs[bb*9 + 0] + intrs[bb*9 + 4]);
    float sc = baseline[bb] * f * (1.f/2048.f);
    const float* dsp = disp + (size_t)bb*HW;

    // phase 1: inline depth+normal -> smem (faithful .view(B,h*w,3) reinterpret)
    for (int k = tid; k < CHSZ; k += 256) {
        int i = ch*CHSZ + k;
        float4 v;
        v.x = sc / dsp[i];
        float nv[3];
#pragma unroll
        for (int tc = 0; tc < 3; tc++) {
            int j = 3*i + tc;
            int c = j >> 15;            // j / HW
            int p = j & (HW-1);
            int py = p >> 8, px = p & (WW-1);
            float dxp = (px < WW-1) ? sc/dsp[p+1]  : 0.f;
            float dxm = (px > 0)    ? sc/dsp[p-1]  : 0.f;
            float dyp = (py < HH-1) ? sc/dsp[p+WW] : 0.f;
            float dym = (py > 0)    ? sc/dsp[p-WW] : 0.f;
            float gx = 0.5f*(dxp - dxm);
            float gy = 0.5f*(dyp - dym);
            float inv = rsqrtf(gx*gx + gy*gy + 1.f);
            nv[tc] = (c == 0) ? -gx*inv : ((c == 1) ? -gy*inv : inv);
        }
        v.y = nv[0]; v.z = nv[1]; v.w = nv[2];
        sdn[k] = v;
    }
    __syncthreads();

    // phase 2: warp w handles planes w, w+8, w+16, w+24
    int wrp = tid >> 5, lane = tid & 31;
    const float* mb = masks + (size_t)bb*MM*HW + (size_t)ch*CHSZ;
#pragma unroll
    for (int mi = 0; mi < 4; mi++) {
        int m = wrp + mi*8;
        const float* mp = mb + (size_t)m*HW;
        float se=0.f, sd=0.f, s0=0.f, s1=0.f, s2=0.f;
#pragma unroll
        for (int jj = 0; jj < 16; jj++) {
            int k = lane + jj*32;
            float e = __expf(mp[k]);    // no max-sub: ratio-invariant, safe range
            float4 v = sdn[k];
            se += e;
            sd = fmaf(e, v.x, sd);
            s0 = fmaf(e, v.y, s0);
            s1 = fmaf(e, v.z, s1);
            s2 = fmaf(e, v.w, s2);
        }
#pragma unroll
        for (int off = 16; off; off >>= 1) {
            se += __shfl_down_sync(0xffffffffu, se, off);
            sd += __shfl_down_sync(0xffffffffu, sd, off);
            s0 += __shfl_down_sync(0xffffffffu, s0, off);
            s1 += __shfl_down_sync(0xffffffffu, s1, off);
            s2 += __shfl_down_sync(0xffffffffu, s2, off);
        }
        if (lane == 0) {
            float* pp = g_part + ((size_t)(bb*MM + m)*5)*NCH + ch;
            pp[0*NCH]=se; pp[1*NCH]=sd; pp[2*NCH]=s0; pp[3*NCH]=s1; pp[4*NCH]=s2;
        }
    }
}

// ---------------- kernel 2: combined (final/border + pool + blend, pipelined) -
__global__ __launch_bounds__(256) void combined_kernel(const float* __restrict__ img,
                                                       const float* __restrict__ masks,
                                                       const float* __restrict__ intrs,
                                                       const float* __restrict__ baseline,
                                                       float* __restrict__ out) {
    int bid = blockIdx.x;
    int tid = threadIdx.x;

    if (bid == 0) {
        // ---------- finalize homographies + zero border, then publish ----------
        {   // thread per (b,m)
            int bm = tid;
            int b  = bm / MM;
            const float* pp = g_part + (size_t)bm*5*NCH;
            float se=0.f, sd=0.f, s0=0.f, s1=0.f, s2=0.f;
#pragma unroll 8
            for (int c = 0; c < NCH; c++) {
                se += pp[0*NCH+c]; sd += pp[1*NCH+c]; s0 += pp[2*NCH+c];
                s1 += pp[3*NCH+c]; s2 += pp[4*NCH+c];
            }
            float inv = 1.f/se;
            float d  = sd*inv;
            float n0 = s0*inv, n1 = s1*inv, n2 = s2*inv;
            float f  = intrs[b*9+0], g = intrs[b*9+4];
            float cx = intrs[b*9+2], cy = intrs[b*9+5];
            float bl = baseline[b];
            float t0 = bl*n0/d, t1 = bl*n1/d, t2 = bl*n2/d;
            float* o = g_Hm + bm*6;
            o[0] = 1.f + cx*t0/f;
            o[1] = cx*t1/g;
            o[2] = cx*t2 - cx*cx*t0/f - cx*cy*t1/g;
            o[3] = cy*t0/f;
            o[4] = 1.f + cy*t1/g;
            o[5] = cy*t2 - cx*cy*t0/f - cy*cy*t1/g;
        }
        for (int e = tid; e < BORDER_ELEMS; e += 256) {
            int b = e / BORDER_PER_B;
            int r = e % BORDER_PER_B;
            int cell;
            if (r < 2*PW)       cell = r;
            else if (r < 4*PW)  cell = (PH-2)*PW + (r - 2*PW);
            else {
                int rr = r - 4*PW;
                int row = rr >> 2, col = rr & 3;
                int cc = (col < 2) ? col : (PW-4 + col);
                cell = (2+row)*PW + cc;
            }
            g_imgp[(size_t)b*PH*PW + cell] = make_float4(0.f,0.f,0.f,0.f);
        }
        __syncthreads();
        if (tid == 0) { __threadfence(); atomicExch(&g_flag, 1); }
        return;
    }

    int r  = bid - 1;
    int b  = r / BATCH_BLKS;
    int q  = r % BATCH_BLKS;

    if (q < POOL_PB) {
        // ---------- pool role: thread per (c,y,x) output of batch b ----------
        int l = q*256 + tid;          // [0, 98304)
        int x = l & (WW-1);
        int t = l >> 8;
        int y = t & (HH-1);
        int c = t >> 7;               // 0..2
        const float* base = img + (((size_t)(b*CC + c)*HF + (size_t)y*8)*WF) + (size_t)x*8;
        float s = 0.f;
#pragma unroll
        for (int rr = 0; rr < 4; rr++) {
            const float4* p = (const float4*)(base + (size_t)rr*WF);
            float4 a = p[0], qq = p[1];
            s += a.x+a.y+a.z+a.w + qq.x+qq.y+qq.z+qq.w;
        }
        float s2 = 0.f;
#pragma unroll
        for (int rr = 4; rr < 8; rr++) {
            const float4* p = (const float4*)(base + (size_t)rr*WF);
            float4 a = p[0], qq = p[1];
            s2 += a.x+a.y+a.z+a.w + qq.x+qq.y+qq.z+qq.w;
        }
        ((float*)&g_imgp[(size_t)b*PH*PW + (size_t)(y+2)*PW + (x+2)])[c] = (s+s2)*(1.f/64.f);
        __syncthreads();
        if (tid == 0) { __threadfence(); atomicAdd(&g_cnt[b], 1); }
    } else {
        // ---------- blend role: waits for Hm/border flag + pool(b) ----------
        if (tid == 0) {
            volatile int* vf = &g_flag;
            volatile int* vc = &g_cnt[b];
            while (*vf == 0) { }
            while (*vc < POOL_PB) { }
        }
        __syncthreads();

        __shared__ float sA[MM][6];
        if (tid < MM) {
            const float* Hp = g_Hm + (b*MM + tid)*6;
            sA[tid][0] = 127.5f*Hp[0];
            sA[tid][1] = 127.5f*Hp[1];
            sA[tid][2] = 127.5f*(Hp[2] + 1.f);
            sA[tid][3] = 63.5f*Hp[3];
            sA[tid][4] = 63.5f*Hp[4];
            sA[tid][5] = 63.5f*(Hp[5] + 1.f);
        }
        __syncthreads();

        int pix = (q - POOL_PB)*256 + tid;
        int y = pix >> 8, x = pix & (WW-1);
        float gxx = -1.f + 2.f*(float)x*(1.f/(float)(WW-1));
        float gyy = -1.f + 2.f*(float)y*(1.f/(float)(HH-1));

        const float* mbase = masks + (size_t)b*MM*HW + pix;
        const float4* ip = g_imgp + (size_t)b*PH*PW;
        float se = 0.f, o0 = 0.f, o1 = 0.f, o2 = 0.f;
#pragma unroll 4
        for (int m = 0; m < MM; m++) {
            float e = __expf(mbase[(size_t)m*HW]);
            se += e;
            float ix = fmaf(sA[m][0], gxx, fmaf(sA[m][1], gyy, sA[m][2]));
            float iy = fmaf(sA[m][3], gxx, fmaf(sA[m][4], gyy, sA[m][5]));
            float x0f = floorf(ix), y0f = floorf(iy);
            float wx = ix - x0f, wy = iy - y0f;
            int xc = (int)fminf(fmaxf(x0f, -2.f), (float)WW);
            int yc = (int)fminf(fmaxf(y0f, -2.f), (float)HH);
            const float4* p00 = ip + (size_t)(yc+2)*PW + (xc+2);
            float4 c00 = p00[0];
            float4 c10 = p00[1];
            float4 c01 = p00[PW];
            float4 c11 = p00[PW+1];
            float w11 = wx*wy;
            float w10 = wx - w11;
            float w01 = wy - w11;
            float w00 = 1.f - wx - w01;
            o0 = fmaf(e, c00.x*w00 + c10.x*w10 + c01.x*w01 + c11.x*w11, o0);
            o1 = fmaf(e, c00.y*w00 + c10.y*w10 + c01.y*w01 + c11.y*w11, o1);
            o2 = fmaf(e, c00.z*w00 + c10.z*w10 + c01.z*w01 + c11.z*w11, o2);
        }
        float inv = 1.f/se;
        out[((size_t)b*3 + 0)*HW + pix] = o0*inv;
        out[((size_t)b*3 + 1)*HW + pix] = o1*inv;
        out[((size_t)b*3 + 2)*HW + pix] = o2*inv;
    }
}

// ---------------- launch -----------------------------------------------------
extern "C" void kernel_launch(void* const* d_in, const int* in_sizes, int n_in,
                              void* d_out, int out_size) {
    const float* img      = (const float*)d_in[0];
    const float* masks    = (const float*)d_in[1];
    const float* disp     = (const float*)d_in[2];
    const float* intrs    = (const float*)d_in[3];
    const float* baseline = (const float*)d_in[4];
    float* out = (float*)d_out;

    plane_partial_kernel<<<BB*NCH, 256>>>(masks, disp, intrs, baseline);
    combined_kernel<<<1 + BB*BATCH_BLKS, 256>>>(img, masks, intrs, baseline, out);
}

// round 6
// speedup vs baseline: 1.2433x; 1.2433x over previous
#include <cuda_runtime.h>
#include <math.h>

// Fixed problem shapes
#define BB 8
#define CC 3
#define HF 1024
#define WF 2048
#define MM 32
#define HH 128
#define WW 256
#define HW (HH*WW)

// padded pooled image (2-px zero border each side)
#define PW (WW+4)
#define PH (HH+4)

#define NCH 64
#define CHSZ (HW/NCH)              // 512 samples per chunk
#define WIN  (3*CHSZ)              // 1536-wide contiguous j-window
#define HALO 257

#define BORDER_PER_B (4*PW + 4*HH)             // 1552
#define BORDER_ELEMS (BB*BORDER_PER_B)         // 12416

// combined-kernel grid roles (strict order: finalize | all pool | all blend)
#define POOL_PB   (CC*HH*WW/32)    // 768 pool blocks per batch (32 out px each)
#define BLEND_PB  128              // blend blocks per batch
#define POOL_BLKS  (BB*POOL_PB)    // 6144
#define BLEND_BLKS (BB*BLEND_PB)   // 1024

// ---------------- scratch ----------------------------------------------------
__device__ float4 g_imgp[BB*PH*PW];          // padded pooled image
__device__ float  g_Hm  [BB*MM*6];           // homography top-2 rows
__device__ float  g_part[BB*MM*5*NCH];       // partial sums [bm][5][NCH]
__device__ int    g_cnt [BB];                // pool completion counters
__device__ int    g_flag;                    // Hm + border ready

// ---------------- kernel 1: plane partials (smem depth window) ---------------
__global__ __launch_bounds__(256) void plane_partial_kernel(const float* __restrict__ masks,
                                                            const float* __restrict__ disp,
                                                            const float* __restrict__ intrs,
                                                            const float* __restrict__ baseline) {
    __shared__ float  sdep[WIN + 2*HALO];    // depth over the j-window (+halo)
    __shared__ float4 sdn [CHSZ];            // {depth, n(3i), n(3i+1), n(3i+2)}
    int blk = blockIdx.x;
    int tid = threadIdx.x;
    if (blk == 0) {                          // reset sync vars (stream-ordered)
        if (tid < BB) g_cnt[tid] = 0;
        if (tid == BB) g_flag = 0;
    }

    int bb = blk / NCH, ch = blk % NCH;
    float f  = 0.5f*(intrs[bb*9 + 0] + intrs[bb*9 + 4]);
    float sc = baseline[bb] * f * (1.f/2048.f);
    const float* dsp = disp + (size_t)bb*HW;
    int S = ch*CHSZ;
    int jbase = 3*S;

    // phase 0: coalesced depth window (one divide per entry)
    for (int k = tid; k < WIN + 2*HALO; k += 256) {
        int jj = jbase + k - HALO;
        jj = min(max(jj, 0), 3*HW - 1);
        sdep[k] = sc / dsp[jj & (HW-1)];
    }
    __syncthreads();

    // phase 1: normals from smem + own depth (faithful .view(B,h*w,3) reinterpret)
    for (int k = tid; k < CHSZ; k += 256) {
        int i = S + k;
        float4 v;
        v.x = sc / dsp[i];
        int k3 = 3*k;
        float nv[3];
#pragma unroll
        for (int tc = 0; tc < 3; tc++) {
            int j  = jbase + k3 + tc;
            int c  = j >> 15;                 // channel of the reinterpret
            int p  = j & (HW-1);
            int px = p & (WW-1), py = p >> 8;
            int kk = HALO + k3 + tc;
            float dxp = (px < WW-1) ? sdep[kk+1]  : 0.f;
            float dxm = (px > 0)    ? sdep[kk-1]  : 0.f;
            float dyp = (py < HH-1) ? sdep[kk+WW] : 0.f;
            float dym = (py > 0)    ? sdep[kk-WW] : 0.f;
            float gx = 0.5f*(dxp - dxm);
            float gy = 0.5f*(dyp - dym);
            float inv = rsqrtf(gx*gx + gy*gy + 1.f);
            nv[tc] = (c == 0) ? -gx*inv : ((c == 1) ? -gy*inv : inv);
        }
        v.y = nv[0]; v.z = nv[1]; v.w = nv[2];
        sdn[k] = v;
    }
    __syncthreads();

    // phase 2: warp w handles planes w, w+8, w+16, w+24
    int wrp = tid >> 5, lane = tid & 31;
    const float* mb = masks + (size_t)bb*MM*HW + (size_t)S;
#pragma unroll
    for (int mi = 0; mi < 4; mi++) {
        int m = wrp + mi*8;
        const float* mp = mb + (size_t)m*HW;
        float se=0.f, sd=0.f, s0=0.f, s1=0.f, s2=0.f;
#pragma unroll
        for (int jj = 0; jj < 16; jj++) {
            int k = lane + jj*32;
            float e = __expf(mp[k]);          // no max-sub: ratio-invariant, safe range
            float4 v = sdn[k];
            se += e;
            sd = fmaf(e, v.x, sd);
            s0 = fmaf(e, v.y, s0);
            s1 = fmaf(e, v.z, s1);
            s2 = fmaf(e, v.w, s2);
        }
#pragma unroll
        for (int off = 16; off; off >>= 1) {
            se += __shfl_down_sync(0xffffffffu, se, off);
            sd += __shfl_down_sync(0xffffffffu, sd, off);
            s0 += __shfl_down_sync(0xffffffffu, s0, off);
            s1 += __shfl_down_sync(0xffffffffu, s1, off);
            s2 += __shfl_down_sync(0xffffffffu, s2, off);
        }
        if (lane == 0) {
            float* pp = g_part + ((size_t)(bb*MM + m)*5)*NCH + ch;
            pp[0*NCH]=se; pp[1*NCH]=sd; pp[2*NCH]=s0; pp[3*NCH]=s1; pp[4*NCH]=s2;
        }
    }
}

// ---------------- kernel 2: combined (finalize | pool | blend) ---------------
__global__ __launch_bounds__(256, 8) void combined_kernel(const float* __restrict__ img,
                                                          const float* __restrict__ masks,
                                                          const float* __restrict__ intrs,
                                                          const float* __restrict__ baseline,
                                                          float* __restrict__ out) {
    __shared__ float sm[256];
    int bid = blockIdx.x;
    int tid = threadIdx.x;

    if (bid == 0) {
        // ---------- finalize homographies + zero border, publish flag ----------
        {
            int bm = tid;                    // 256 (b,m) pairs
            int b  = bm / MM;
            const float* pp = g_part + (size_t)bm*5*NCH;
            float se=0.f, sd=0.f, s0=0.f, s1=0.f, s2=0.f;
#pragma unroll 8
            for (int c = 0; c < NCH; c++) {
                se += pp[0*NCH+c]; sd += pp[1*NCH+c]; s0 += pp[2*NCH+c];
                s1 += pp[3*NCH+c]; s2 += pp[4*NCH+c];
            }
            float inv = 1.f/se;
            float d  = sd*inv;
            float n0 = s0*inv, n1 = s1*inv, n2 = s2*inv;
            float f  = intrs[b*9+0], g = intrs[b*9+4];
            float cx = intrs[b*9+2], cy = intrs[b*9+5];
            float bl = baseline[b];
            float t0 = bl*n0/d, t1 = bl*n1/d, t2 = bl*n2/d;
            float* o = g_Hm + bm*6;
            o[0] = 1.f + cx*t0/f;
            o[1] = cx*t1/g;
            o[2] = cx*t2 - cx*cx*t0/f - cx*cy*t1/g;
            o[3] = cy*t0/f;
            o[4] = 1.f + cy*t1/g;
            o[5] = cy*t2 - cx*cy*t0/f - cy*cy*t1/g;
        }
        for (int e = tid; e < BORDER_ELEMS; e += 256) {
            int b = e / BORDER_PER_B;
            int r = e % BORDER_PER_B;
            int cell;
            if (r < 2*PW)       cell = r;
            else if (r < 4*PW)  cell = (PH-2)*PW + (r - 2*PW);
            else {
                int rr = r - 4*PW;
                int row = rr >> 2, col = rr & 3;
                int cc = (col < 2) ? col : (PW-4 + col);
                cell = (2+row)*PW + cc;
            }
            g_imgp[(size_t)b*PH*PW + cell] = make_float4(0.f,0.f,0.f,0.f);
        }
        __syncthreads();
        if (tid == 0) { __threadfence(); atomicExch(&g_flag, 1); }
        return;
    }

    if (bid <= POOL_BLKS) {
        // ---------- pool role: 32 out px of one (b,c,y); warp r loads row r ----
        int r0 = bid - 1;
        int b  = r0 / POOL_PB;
        int q  = r0 % POOL_PB;
        int lane = tid & 31, r = tid >> 5;
        int l  = q * 32;
        int x0 = l & (WW-1);
        int t  = l >> 8;
        int y  = t & (HH-1);
        int c  = t >> 7;

        const float4* p = (const float4*)(img +
            (((size_t)(b*CC + c)*HF + (size_t)y*8 + r)*WF) + (size_t)(x0 + lane)*8);
        float4 a = p[0], q4 = p[1];
        sm[r*32 + lane] = a.x+a.y+a.z+a.w + q4.x+q4.y+q4.z+q4.w;
        __syncthreads();
        if (tid < 32) {
            float acc = 0.f;
#pragma unroll
            for (int rr = 0; rr < 8; rr++) acc += sm[rr*32 + tid];
            ((float*)&g_imgp[(size_t)b*PH*PW + (size_t)(y+2)*PW + (x0 + tid + 2)])[c]
                = acc * (1.f/64.f);
        }
        __syncthreads();
        if (tid == 0) { __threadfence(); atomicAdd(&g_cnt[b], 1); }
        return;
    }

    // ---------- blend role (all bids after all pool bids) ----------
    int rel = bid - 1 - POOL_BLKS;
    int b   = rel / BLEND_PB;
    if (tid == 0) {
        volatile int* vf = &g_flag;
        volatile int* vc = &g_cnt[b];
        while (*vf == 0)        { __nanosleep(64); }
        while (*vc < POOL_PB)   { __nanosleep(64); }
        __threadfence();
    }
    __syncthreads();

    __shared__ float sA[MM][6];
    if (tid < MM) {
        const float* Hp = g_Hm + (b*MM + tid)*6;
        sA[tid][0] = 127.5f*Hp[0];
        sA[tid][1] = 127.5f*Hp[1];
        sA[tid][2] = 127.5f*(Hp[2] + 1.f);
        sA[tid][3] = 63.5f*Hp[3];
        sA[tid][4] = 63.5f*Hp[4];
        sA[tid][5] = 63.5f*(Hp[5] + 1.f);
    }
    __syncthreads();

    int pix = (rel % BLEND_PB)*256 + tid;
    int y = pix >> 8, x = pix & (WW-1);
    float gxx = -1.f + 2.f*(float)x*(1.f/(float)(WW-1));
    float gyy = -1.f + 2.f*(float)y*(1.f/(float)(HH-1));

    const float* mbase = masks + (size_t)b*MM*HW + pix;
    const float4* ip = g_imgp + (size_t)b*PH*PW;
    float se = 0.f, o0 = 0.f, o1 = 0.f, o2 = 0.f;
#pragma unroll 4
    for (int m = 0; m < MM; m++) {
        float e = __expf(mbase[(size_t)m*HW]);
        se += e;
        float ix = fmaf(sA[m][0], gxx, fmaf(sA[m][1], gyy, sA[m][2]));
        float iy = fmaf(sA[m][3], gxx, fmaf(sA[m][4], gyy, sA[m][5]));
        float x0f = floorf(ix), y0f = floorf(iy);
        float wx = ix - x0f, wy = iy - y0f;
        int xc = (int)fminf(fmaxf(x0f, -2.f), (float)WW);
        int yc = (int)fminf(fmaxf(y0f, -2.f), (float)HH);
        const float4* p00 = ip + (size_t)(yc+2)*PW + (xc+2);
        float4 c00 = p00[0];
        float4 c10 = p00[1];
        float4 c01 = p00[PW];
        float4 c11 = p00[PW+1];
        float w11 = wx*wy;
        float w10 = wx - w11;
        float w01 = wy - w11;
        float w00 = 1.f - wx - w01;
        o0 = fmaf(e, c00.x*w00 + c10.x*w10 + c01.x*w01 + c11.x*w11, o0);
        o1 = fmaf(e, c00.y*w00 + c10.y*w10 + c01.y*w01 + c11.y*w11, o1);
        o2 = fmaf(e, c00.z*w00 + c10.z*w10 + c01.z*w01 + c11.z*w11, o2);
    }
    float inv = 1.f/se;
    out[((size_t)b*3 + 0)*HW + pix] = o0*inv;
    out[((size_t)b*3 + 1)*HW + pix] = o1*inv;
    out[((size_t)b*3 + 2)*HW + pix] = o2*inv;
}

// ---------------- launch -----------------------------------------------------
extern "C" void kernel_launch(void* const* d_in, const int* in_sizes, int n_in,
                              void* d_out, int out_size) {
    const float* img      = (const float*)d_in[0];
    const float* masks    = (const float*)d_in[1];
    const float* disp     = (const float*)d_in[2];
    const float* intrs    = (const float*)d_in[3];
    const float* baseline = (const float*)d_in[4];
    float* out = (float*)d_out;

    plane_partial_kernel<<<BB*NCH, 256>>>(masks, disp, intrs, baseline);
    combined_kernel<<<1 + POOL_BLKS + BLEND_BLKS, 256>>>(img, masks, intrs, baseline, out);
}

// round 7
// speedup vs baseline: 1.5421x; 1.2403x over previous
#include <cuda_runtime.h>
#include <math.h>

// Fixed problem shapes
#define BB 8
#define CC 3
#define HF 1024
#define WF 2048
#define MM 32
#define HH 128
#define WW 256
#define HW (HH*WW)

// padded pooled image (2-px zero border each side)
#define PW (WW+4)
#define PH (HH+4)

#define NCH 64
#define CHSZ (HW/NCH)              // 512 samples per chunk
#define WIN  (3*CHSZ)              // 1536-wide contiguous j-window
#define HALO 257

#define BORDER_PER_B (4*PW + 4*HH)             // 1552
#define BORDER_ELEMS (BB*BORDER_PER_B)         // 12416

#define PLANE_BLKS (BB*NCH)                    // 512
#define POOL_BLKS  (BB*CC*HH*WW/32)            // 24576

// ---------------- scratch ----------------------------------------------------
__device__ float4 g_imgp[BB*PH*PW];          // padded pooled image
__device__ float  g_Hm  [BB*MM*6];           // homography top-2 rows
__device__ float  g_part[BB*MM*5*NCH];       // partial sums [bm][5][NCH]

// ---------------- kernel 1: fused producers (plane partials | pool) ----------
__global__ __launch_bounds__(256, 7) void producer_kernel(const float* __restrict__ img,
                                                          const float* __restrict__ masks,
                                                          const float* __restrict__ disp,
                                                          const float* __restrict__ intrs,
                                                          const float* __restrict__ baseline) {
    __shared__ float  sdep[WIN + 2*HALO];    // plane role: depth window (+halo)
    __shared__ float4 sdn [CHSZ];            // plane role: {depth, n0, n1, n2}
    __shared__ float  sm  [256];             // pool role: row partials
    int bid = blockIdx.x;
    int tid = threadIdx.x;

    if (bid < PLANE_BLKS) {
        // ---------------- plane-partial role ----------------
        int bb = bid / NCH, ch = bid % NCH;
        float f  = 0.5f*(intrs[bb*9 + 0] + intrs[bb*9 + 4]);
        float sc = baseline[bb] * f * (1.f/2048.f);
        const float* dsp = disp + (size_t)bb*HW;
        int S = ch*CHSZ;
        int jbase = 3*S;

        // phase 0: coalesced depth window (one divide per entry)
        for (int k = tid; k < WIN + 2*HALO; k += 256) {
            int jj = jbase + k - HALO;
            jj = min(max(jj, 0), 3*HW - 1);
            sdep[k] = sc / dsp[jj & (HW-1)];
        }
        __syncthreads();

        // phase 1: normals from smem (faithful .view(B,h*w,3) reinterpret)
        for (int k = tid; k < CHSZ; k += 256) {
            int i = S + k;
            float4 v;
            v.x = sc / dsp[i];
            int k3 = 3*k;
            float nv[3];
#pragma unroll
            for (int tc = 0; tc < 3; tc++) {
                int j  = jbase + k3 + tc;
                int c  = j >> 15;
                int p  = j & (HW-1);
                int px = p & (WW-1), py = p >> 8;
                int kk = HALO + k3 + tc;
                float dxp = (px < WW-1) ? sdep[kk+1]  : 0.f;
                float dxm = (px > 0)    ? sdep[kk-1]  : 0.f;
                float dyp = (py < HH-1) ? sdep[kk+WW] : 0.f;
                float dym = (py > 0)    ? sdep[kk-WW] : 0.f;
                float gx = 0.5f*(dxp - dxm);
                float gy = 0.5f*(dyp - dym);
                float inv = rsqrtf(gx*gx + gy*gy + 1.f);
                nv[tc] = (c == 0) ? -gx*inv : ((c == 1) ? -gy*inv : inv);
            }
            v.y = nv[0]; v.z = nv[1]; v.w = nv[2];
            sdn[k] = v;
        }
        __syncthreads();

        // phase 2: warp w handles planes w, w+8, w+16, w+24
        int wrp = tid >> 5, lane = tid & 31;
        const float* mb = masks + (size_t)bb*MM*HW + (size_t)S;
#pragma unroll
        for (int mi = 0; mi < 4; mi++) {
            int m = wrp + mi*8;
            const float* mp = mb + (size_t)m*HW;
            float se=0.f, sd=0.f, s0=0.f, s1=0.f, s2=0.f;
#pragma unroll
            for (int jj = 0; jj < 16; jj++) {
                int k = lane + jj*32;
                float e = __expf(mp[k]);     // no max-sub: ratio-invariant, safe range
                float4 v = sdn[k];
                se += e;
                sd = fmaf(e, v.x, sd);
                s0 = fmaf(e, v.y, s0);
                s1 = fmaf(e, v.z, s1);
                s2 = fmaf(e, v.w, s2);
            }
#pragma unroll
            for (int off = 16; off; off >>= 1) {
                se += __shfl_down_sync(0xffffffffu, se, off);
                sd += __shfl_down_sync(0xffffffffu, sd, off);
                s0 += __shfl_down_sync(0xffffffffu, s0, off);
                s1 += __shfl_down_sync(0xffffffffu, s1, off);
                s2 += __shfl_down_sync(0xffffffffu, s2, off);
            }
            if (lane == 0) {
                float* pp = g_part + ((size_t)(bb*MM + m)*5)*NCH + ch;
                pp[0*NCH]=se; pp[1*NCH]=sd; pp[2*NCH]=s0; pp[3*NCH]=s1; pp[4*NCH]=s2;
            }
        }
        return;
    }

    // ---------------- pool role: 32 out px of one (b,c,y); warp r loads row r --
    int r0 = bid - PLANE_BLKS;
    int lane = tid & 31, r = tid >> 5;
    int l  = r0 * 32;                 // linear over (b,c,y,x32)
    int x0 = l & (WW-1);
    int t  = l >> 8;
    int y  = t & (HH-1);  t >>= 7;
    int c  = t % CC;
    int b  = t / CC;

    const float4* p = (const float4*)(img +
        (((size_t)(b*CC + c)*HF + (size_t)y*8 + r)*WF) + (size_t)(x0 + lane)*8);
    float4 a = __ldcs(p), q4 = __ldcs(p + 1);   // streaming: don't pollute L1
    sm[r*32 + lane] = a.x+a.y+a.z+a.w + q4.x+q4.y+q4.z+q4.w;
    __syncthreads();
    if (tid < 32) {
        float acc = 0.f;
#pragma unroll
        for (int rr = 0; rr < 8; rr++) acc += sm[rr*32 + tid];
        ((float*)&g_imgp[(size_t)b*PH*PW + (size_t)(y+2)*PW + (x0 + tid + 2)])[c]
            = acc * (1.f/64.f);
    }
}

// ---------------- kernel 2: finalize homographies + border zero --------------
__global__ void finalize_kernel(const float* __restrict__ intrs,
                                const float* __restrict__ baseline) {
    int bm = blockIdx.x;              // 256 blocks = (b,m)
    int c  = threadIdx.x;             // 64 threads
    int lane = c & 31, w = c >> 5;

    // border zero: global thread over 16384 covers 12416 border cells
    int gt = bm*64 + c;
    if (gt < BORDER_ELEMS) {
        int b = gt / BORDER_PER_B;
        int r = gt % BORDER_PER_B;
        int cell;
        if (r < 2*PW)       cell = r;
        else if (r < 4*PW)  cell = (PH-2)*PW + (r - 2*PW);
        else {
            int rr = r - 4*PW;
            int row = rr >> 2, col = rr & 3;
            int cc = (col < 2) ? col : (PW-4 + col);
            cell = (2+row)*PW + cc;
        }
        g_imgp[(size_t)b*PH*PW + cell] = make_float4(0.f,0.f,0.f,0.f);
    }

    const float* pp = g_part + (size_t)bm*5*NCH;
    float v[5];
#pragma unroll
    for (int s = 0; s < 5; s++) v[s] = pp[s*NCH + c];
#pragma unroll
    for (int off = 16; off; off >>= 1)
#pragma unroll
        for (int s = 0; s < 5; s++) v[s] += __shfl_down_sync(0xffffffffu, v[s], off);
    __shared__ float sw[2][5];
    if (lane == 0)
#pragma unroll
        for (int s = 0; s < 5; s++) sw[w][s] = v[s];
    __syncthreads();
    if (c == 0) {
        float se = sw[0][0]+sw[1][0];
        float sd = sw[0][1]+sw[1][1];
        float s0 = sw[0][2]+sw[1][2];
        float s1 = sw[0][3]+sw[1][3];
        float s2 = sw[0][4]+sw[1][4];
        int b = bm / MM;
        float inv = 1.f/se;
        float d  = sd*inv;
        float n0 = s0*inv, n1 = s1*inv, n2 = s2*inv;
        float f  = intrs[b*9+0], g = intrs[b*9+4];
        float cx = intrs[b*9+2], cy = intrs[b*9+5];
        float bl = baseline[b];
        float t0 = bl*n0/d, t1 = bl*n1/d, t2 = bl*n2/d;
        float* o = g_Hm + bm*6;
        o[0] = 1.f + cx*t0/f;
        o[1] = cx*t1/g;
        o[2] = cx*t2 - cx*cx*t0/f - cx*cy*t1/g;
        o[3] = cy*t0/f;
        o[4] = 1.f + cy*t1/g;
        o[5] = cy*t2 - cx*cy*t0/f - cy*cy*t1/g;
    }
}

// ---------------- kernel 3: blend (2-way plane split, 512 thr/block) ---------
__global__ __launch_bounds__(512, 3) void blend_kernel(const float* __restrict__ masks,
                                                       float* __restrict__ out) {
    __shared__ float4 sA4[MM][2];     // {127.5*a,127.5*b,127.5*(c+1)} / {63.5*d,...}
    __shared__ float  sred[4][256];
    int b   = blockIdx.x >> 7;        // 1024 blocks: 8 batches x 128
    int loc = blockIdx.x & 127;
    int tid = threadIdx.x;
    int half = tid >> 8;              // 0: planes 0-15, 1: planes 16-31
    int pi   = tid & 255;

    if (tid < MM) {
        const float* Hp = g_Hm + (b*MM + tid)*6;
        sA4[tid][0] = make_float4(127.5f*Hp[0], 127.5f*Hp[1], 127.5f*(Hp[2]+1.f), 0.f);
        sA4[tid][1] = make_float4(63.5f*Hp[3],  63.5f*Hp[4],  63.5f*(Hp[5]+1.f),  0.f);
    }
    __syncthreads();

    int pix = loc*256 + pi;
    int y = pix >> 8, x = pix & (WW-1);
    float gxx = -1.f + 2.f*(float)x*(1.f/(float)(WW-1));
    float gyy = -1.f + 2.f*(float)y*(1.f/(float)(HH-1));

    const float* mbase = masks + (size_t)b*MM*HW + (size_t)half*16*HW + pix;
    const float4* ip = g_imgp + (size_t)b*PH*PW;
    float se = 0.f, o0 = 0.f, o1 = 0.f, o2 = 0.f;
#pragma unroll 4
    for (int mi = 0; mi < 16; mi++) {
        int m = half*16 + mi;
        float e = __expf(mbase[(size_t)mi*HW]);
        se += e;
        float4 cA = sA4[m][0];
        float4 cB = sA4[m][1];
        float ix = fmaf(cA.x, gxx, fmaf(cA.y, gyy, cA.z));
        float iy = fmaf(cB.x, gxx, fmaf(cB.y, gyy, cB.z));
        float x0f = floorf(ix), y0f = floorf(iy);
        float wx = ix - x0f, wy = iy - y0f;
        int xc = (int)fminf(fmaxf(x0f, -2.f), (float)WW);
        int yc = (int)fminf(fmaxf(y0f, -2.f), (float)HH);
        const float4* p00 = ip + (size_t)(yc+2)*PW + (xc+2);
        float4 c00 = p00[0];
        float4 c10 = p00[1];
        float4 c01 = p00[PW];
        float4 c11 = p00[PW+1];
        float w11 = wx*wy;
        float w10 = wx - w11;
        float w01 = wy - w11;
        float w00 = 1.f - wx - w01;
        o0 = fmaf(e, c00.x*w00 + c10.x*w10 + c01.x*w01 + c11.x*w11, o0);
        o1 = fmaf(e, c00.y*w00 + c10.y*w10 + c01.y*w01 + c11.y*w11, o1);
        o2 = fmaf(e, c00.z*w00 + c10.z*w10 + c01.z*w01 + c11.z*w11, o2);
    }

    if (half) { sred[0][pi]=se; sred[1][pi]=o0; sred[2][pi]=o1; sred[3][pi]=o2; }
    __syncthreads();
    if (!half) {
        se += sred[0][pi]; o0 += sred[1][pi]; o1 += sred[2][pi]; o2 += sred[3][pi];
        float inv = 1.f/se;
        out[((size_t)b*3 + 0)*HW + pix] = o0*inv;
        out[((size_t)b*3 + 1)*HW + pix] = o1*inv;
        out[((size_t)b*3 + 2)*HW + pix] = o2*inv;
    }
}

// ---------------- launch -----------------------------------------------------
extern "C" void kernel_launch(void* const* d_in, const int* in_sizes, int n_in,
                              void* d_out, int out_size) {
    const float* img      = (const float*)d_in[0];
    const float* masks    = (const float*)d_in[1];
    const float* disp     = (const float*)d_in[2];
    const float* intrs    = (const float*)d_in[3];
    const float* baseline = (const float*)d_in[4];
    float* out = (float*)d_out;

    producer_kernel<<<PLANE_BLKS + POOL_BLKS, 256>>>(img, masks, disp, intrs, baseline);
    finalize_kernel<<<BB*MM, 64>>>(intrs, baseline);
    blend_kernel<<<BB*128, 512>>>(masks, out);
}